// round 5
// baseline (speedup 1.0000x reference)
#include <cuda_runtime.h>
#include <math.h>

#define MAX_IN 64
#define D_MODEL 64
#define ROWS_PER_BLOCK 16
#define THREADS 256
#define MAXN (1 << 17)

__device__ int g_idx[MAXN];
__device__ int g_cnt[65];
__device__ int g_base[65];

__device__ __forceinline__ float fast_tanh(float x) {
    float y;
    asm("tanh.approx.f32 %0, %1;" : "=f"(y) : "f"(x));
    return y;
}

__device__ __forceinline__ float gelu_tanh(float v) {
    const float c = 0.7978845608028654f;
    float u = c * (v + 0.044715f * v * v * v);
    return 0.5f * v * (1.0f + fast_tanh(u));
}

// ---------- sort pre-pass ----------
__global__ void k_zero() {
    if (threadIdx.x < 65) g_cnt[threadIdx.x] = 0;
}

__global__ void k_hist(const int* __restrict__ lengths, int n) {
    __shared__ int h[65];
    int tid = threadIdx.x;
    if (tid < 65) h[tid] = 0;
    __syncthreads();
    int r = blockIdx.x * blockDim.x + tid;
    if (r < n) {
        int len = lengths[r];
        len = max(1, min(64, len));
        atomicAdd(&h[len], 1);
    }
    __syncthreads();
    if (tid < 65 && h[tid] > 0) atomicAdd(&g_cnt[tid], h[tid]);
}

__global__ void k_scan() {
    // descending length order: longest rows first
    int off = 0;
    for (int len = 64; len >= 1; --len) {
        g_base[len] = off;
        off += g_cnt[len];
    }
}

__global__ void k_scatter(const int* __restrict__ lengths, int n) {
    __shared__ int h[65];
    __shared__ int bbase[65];
    int tid = threadIdx.x;
    if (tid < 65) h[tid] = 0;
    __syncthreads();
    int r = blockIdx.x * blockDim.x + tid;
    int len = 0, myrank = 0;
    if (r < n) {
        len = lengths[r];
        len = max(1, min(64, len));
        myrank = atomicAdd(&h[len], 1);
    }
    __syncthreads();
    if (tid < 65 && h[tid] > 0) bbase[tid] = atomicAdd(&g_base[tid], h[tid]);
    __syncthreads();
    if (r < n) g_idx[bbase[len] + myrank] = r;
}

// ---------- main kernel (R3 inner loop + row indirection) ----------
__global__ __launch_bounds__(THREADS, 6)
void fe_kernel(const float* __restrict__ seg,
               const float* __restrict__ W,
               const float* __restrict__ b,
               const int*   __restrict__ lengths,
               float* __restrict__ out,
               int n, int use_idx)
{
    __shared__ float sx[ROWS_PER_BLOCK][MAX_IN];
    __shared__ int   slen[ROWS_PER_BLOCK];
    __shared__ int   sidx[ROWS_PER_BLOCK];

    const int row0 = blockIdx.x * ROWS_PER_BLOCK;
    const int tid  = threadIdx.x;

    if (tid < ROWS_PER_BLOCK) {
        int r = row0 + tid;
        int src = 0, len = 0;
        if (r < n) {
            src = use_idx ? g_idx[r] : r;
            len = lengths[src];
        }
        sidx[tid] = src;
        slen[tid] = len;
    }
    __syncthreads();

    // Cooperative masked load of x rows into smem
    {
        int r  = tid >> 4;
        int c4 = tid & 15;
        float4 v = make_float4(0.f, 0.f, 0.f, 0.f);
        int len = slen[r];
        if (len > 0) {
            int src = sidx[r];
            v = reinterpret_cast<const float4*>(seg)[(size_t)src * 16 + c4];
            int c = c4 * 4;
            if (c + 0 >= len) v.x = 0.f;
            if (c + 1 >= len) v.y = 0.f;
            if (c + 2 >= len) v.z = 0.f;
            if (c + 3 >= len) v.w = 0.f;
        }
        *reinterpret_cast<float4*>(&sx[r][c4 * 4]) = v;
    }
    __syncthreads();

    const int g = tid >> 4;
    const int t = tid & 15;
    const int len = slen[g];
    if (len == 0) return;
    const int src = sidx[g];

    const int len4 = (len + 3) & ~3;
    const float4* Wr = reinterpret_cast<const float4*>(W) + (size_t)src * 1024 + t;
    const float* xr = sx[g];

    float4 acc = make_float4(0.f, 0.f, 0.f, 0.f);

    #pragma unroll 1
    for (int i = 0; i < len4; i += 4) {
        float4 w0 = Wr[(i + 0) * 16];
        float4 w1 = Wr[(i + 1) * 16];
        float4 w2 = Wr[(i + 2) * 16];
        float4 w3 = Wr[(i + 3) * 16];
        float4 xv = *reinterpret_cast<const float4*>(xr + i);
        acc.x += xv.x * w0.x + xv.y * w1.x + xv.z * w2.x + xv.w * w3.x;
        acc.y += xv.x * w0.y + xv.y * w1.y + xv.z * w2.y + xv.w * w3.y;
        acc.z += xv.x * w0.z + xv.y * w1.z + xv.z * w2.z + xv.w * w3.z;
        acc.w += xv.x * w0.w + xv.y * w1.w + xv.z * w2.w + xv.w * w3.w;
    }

    float4 bb = reinterpret_cast<const float4*>(b)[(size_t)src * 16 + t];
    float4 r4;
    r4.x = gelu_tanh(acc.x + bb.x);
    r4.y = gelu_tanh(acc.y + bb.y);
    r4.z = gelu_tanh(acc.z + bb.z);
    r4.w = gelu_tanh(acc.w + bb.w);

    reinterpret_cast<float4*>(out)[(size_t)src * 16 + t] = r4;
}

extern "C" void kernel_launch(void* const* d_in, const int* in_sizes, int n_in,
                              void* d_out, int out_size) {
    const float* seg     = (const float*)d_in[0];
    const float* W       = (const float*)d_in[1];
    const float* b       = (const float*)d_in[2];
    const int*   lengths = (const int*)d_in[3];
    float* out = (float*)d_out;

    int n = in_sizes[3];
    int grid  = (n + ROWS_PER_BLOCK - 1) / ROWS_PER_BLOCK;
    int sgrid = (n + THREADS - 1) / THREADS;

    int use_idx = (n <= MAXN) ? 1 : 0;
    if (use_idx) {
        k_zero<<<1, 65>>>();
        k_hist<<<sgrid, THREADS>>>(lengths, n);
        k_scan<<<1, 1>>>();
        k_scatter<<<sgrid, THREADS>>>(lengths, n);
    }
    fe_kernel<<<grid, THREADS>>>(seg, W, b, lengths, out, n, use_idx);
}